// round 15
// baseline (speedup 1.0000x reference)
#include <cuda_runtime.h>
#include <cuda_bf16.h>
#include <cstdint>

#define E_TOTAL   32768
#define FEAT_DIM  17
#define HID       64
#define R_DIM     768
#define OUT_PER_EDGE 2304
#define LN_EPS    1e-5f

#define EPC       128                 // edges per CTA
#define NCTA      (E_TOTAL / EPC)     // 256
#define KB        128                 // B row: [bhi(64) | blo(64)]
#define CCOLS     48                  // cols per chunk
#define NCH       (R_DIM / CCOLS)     // 16
#define BST2      136                 // smem B row stride (bf16)
#define RBS       68                  // rbuf row stride (floats)
#define SA_ST     68                  // sA row stride (u32): [hi(32)|lo(32)|pad]
#define H_ST      66                  // h row stride (floats)

// main-loop smem byte offsets
#define OFF_RBUF  0                   // [128][68] f32    34816 B
#define OFF_SBAS  34816               // [128][40] f32    20480 B
#define OFF_SB3   55296               // [768] f32         3072 B
#define OFF_SB    58368               // [48][136] bf16   13056 B
#define SM_TOTAL  71424
// prologue aliases: h [0,33792) ; sA [0,34816) ; weights:
#define OFF_PW1   36864
#define OFF_PW2   (OFF_PW1 + FEAT_DIM * HID * 4)   // 41216
#define OFF_PB    (OFF_PW2 + HID * HID * 4)        // 57600: b1|g1|b2|g2

// B: [n][128] bf16 = [bhi(64) | blo(64)]
__device__ __nv_bfloat16 g_bbf[R_DIM * KB];

__device__ __forceinline__ float silu_f(float x) { return x / (1.0f + __expf(-x)); }

__device__ __forceinline__ uint32_t smem_u32(const void* p) {
    uint32_t a;
    asm("{ .reg .u64 t; cvta.to.shared.u64 t, %1; cvt.u32.u64 %0, t; }" : "=r"(a) : "l"(p));
    return a;
}
__device__ __forceinline__ void cp_async16(uint32_t dst, const void* src) {
    asm volatile("cp.async.ca.shared.global [%0], [%1], 16;" :: "r"(dst), "l"(src));
}
#define CP_COMMIT() asm volatile("cp.async.commit_group;" ::: "memory")
#define CP_WAIT0()  asm volatile("cp.async.wait_group 0;" ::: "memory")

__device__ __forceinline__ void mma_bf16(float& d0, float& d1, float& d2, float& d3,
                                         uint32_t a0, uint32_t a1, uint32_t a2, uint32_t a3,
                                         uint32_t b0, uint32_t b1) {
    asm volatile(
        "mma.sync.aligned.m16n8k16.row.col.f32.bf16.bf16.f32 "
        "{%0,%1,%2,%3}, {%4,%5,%6,%7}, {%8,%9}, {%0,%1,%2,%3};"
        : "+f"(d0), "+f"(d1), "+f"(d2), "+f"(d3)
        : "r"(a0), "r"(a1), "r"(a2), "r"(a3), "r"(b0), "r"(b1));
}

// ---------------------------------------------------------------------------
// k0: B prep. g_bbf[n][kk]: kk<64 -> hi(W3[k][n]), else lo residual.
// ---------------------------------------------------------------------------
__global__ __launch_bounds__(256) void k0_prep(const float* __restrict__ W3) {
    int i = blockIdx.x * 256 + threadIdx.x;
    if (i >= R_DIM * KB) return;
    const int n = i >> 7, kk = i & 127;
    const int phase = kk >> 6, k = kk & 63;
    const float wv = W3[k * R_DIM + n];
    const __nv_bfloat16 hi = __float2bfloat16(wv);
    g_bbf[i] = phase ? __float2bfloat16(wv - __bfloat162float(hi)) : hi;
}

// ---------------------------------------------------------------------------
// k2: fused radial-MLP prologue + split-K mma.sync GEMM + tensor product.
// A frags: 8 distinct (hi 0-3, lo 4-7); 3-term split = ahi*bhi + alo*bhi +
// ahi*blo with bhi frags reused. Single smem B buffer, cp.async prefetch
// overlapped with the TP phase. 3 CTAs/SM.
// ---------------------------------------------------------------------------
__global__ __launch_bounds__(256, 3) void k2_fused(
    const float* __restrict__ feat,
    const float* __restrict__ basis,
    const float* __restrict__ W1, const float* __restrict__ b1, const float* __restrict__ g1,
    const float* __restrict__ W2, const float* __restrict__ b2, const float* __restrict__ g2,
    const float* __restrict__ b3,
    float* __restrict__ out)
{
    extern __shared__ __align__(16) char smem[];
    float* rbuf = (float*)(smem + OFF_RBUF);
    float* sbas = (float*)(smem + OFF_SBAS);
    float* sb3  = (float*)(smem + OFF_SB3);
    __nv_bfloat16* sB = (__nv_bfloat16*)(smem + OFF_SB);
    const uint32_t sB_u = smem_u32(smem) + OFF_SB;

    const int t = threadIdx.x;
    const int w = t >> 5, l = t & 31;
    const int g = l >> 2, tig = l & 3;
    const int e0 = blockIdx.x * EPC;

    // ================= prologue: radial MLP for this CTA's 128 edges =======
    {
        float* sW1p = (float*)(smem + OFF_PW1);
        float* sW2p = (float*)(smem + OFF_PW2);
        float* pb   = (float*)(smem + OFF_PB);   // [b1|g1|b2|g2] x64
        for (int i = t; i < FEAT_DIM * HID; i += 256) sW1p[i] = W1[i];
        for (int i = t; i < HID * HID;     i += 256) sW2p[i] = W2[i];
        if (t < HID) { pb[t] = b1[t]; pb[64 + t] = g1[t]; pb[128 + t] = b2[t]; pb[192 + t] = g2[t]; }
        __syncthreads();

        const int eL = t >> 1, half = t & 1, jb = 32 * half;
        const float* fr = feat + (size_t)(e0 + eL) * FEAT_DIM;
        float* hrow = (float*)smem + eL * H_ST;

        float x[32];
#pragma unroll
        for (int jj = 0; jj < 32; jj++) x[jj] = pb[jb + jj];
#pragma unroll 1
        for (int c = 0; c < FEAT_DIM; c++) {
            const float fv = fr[c];
            const float4* w4 = (const float4*)(sW1p + c * HID + jb);
#pragma unroll
            for (int j4 = 0; j4 < 8; j4++) {
                float4 wv = w4[j4];
                x[4*j4+0] = fmaf(fv, wv.x, x[4*j4+0]);
                x[4*j4+1] = fmaf(fv, wv.y, x[4*j4+1]);
                x[4*j4+2] = fmaf(fv, wv.z, x[4*j4+2]);
                x[4*j4+3] = fmaf(fv, wv.w, x[4*j4+3]);
            }
        }
        {
            float s = 0.f, q = 0.f;
#pragma unroll
            for (int jj = 0; jj < 32; jj++) { x[jj] = silu_f(x[jj]); s += x[jj]; q += x[jj]*x[jj]; }
            s += __shfl_xor_sync(0xffffffffu, s, 1);
            q += __shfl_xor_sync(0xffffffffu, q, 1);
            const float mu = s * (1.0f/64.0f);
            const float var = q * (1.0f/64.0f) - mu*mu;
            const float rs = rsqrtf(var + LN_EPS);
#pragma unroll
            for (int jj = 0; jj < 32; jj++)
                hrow[jb + jj] = (x[jj] - mu) * rs * pb[64 + jb + jj];
        }
        __syncwarp();

        // layer 2
#pragma unroll
        for (int jj = 0; jj < 32; jj++) x[jj] = pb[128 + jb + jj];
#pragma unroll 1
        for (int k = 0; k < HID; k++) {
            const float hv = hrow[k];
            const float4* w4 = (const float4*)(sW2p + k * HID + jb);
#pragma unroll
            for (int j4 = 0; j4 < 8; j4++) {
                float4 wv = w4[j4];
                x[4*j4+0] = fmaf(hv, wv.x, x[4*j4+0]);
                x[4*j4+1] = fmaf(hv, wv.y, x[4*j4+1]);
                x[4*j4+2] = fmaf(hv, wv.z, x[4*j4+2]);
                x[4*j4+3] = fmaf(hv, wv.w, x[4*j4+3]);
            }
        }
        float s = 0.f, q = 0.f;
#pragma unroll
        for (int jj = 0; jj < 32; jj++) { x[jj] = silu_f(x[jj]); s += x[jj]; q += x[jj]*x[jj]; }
        s += __shfl_xor_sync(0xffffffffu, s, 1);
        q += __shfl_xor_sync(0xffffffffu, q, 1);
        const float mu = s * (1.0f/64.0f);
        const float var = q * (1.0f/64.0f) - mu*mu;
        const float rs = rsqrtf(var + LN_EPS);

        uint32_t hi16[16], lo16[16];
#pragma unroll
        for (int p = 0; p < 16; p++) {
            const float h0 = (x[2*p]   - mu) * rs * pb[192 + jb + 2*p];
            const float h1 = (x[2*p+1] - mu) * rs * pb[192 + jb + 2*p+1];
            const __nv_bfloat16 a0 = __float2bfloat16(h0), a1 = __float2bfloat16(h1);
            const __nv_bfloat16 c0 = __float2bfloat16(h0 - __bfloat162float(a0));
            const __nv_bfloat16 c1 = __float2bfloat16(h1 - __bfloat162float(a1));
            hi16[p] = (uint32_t)__bfloat16_as_ushort(a0) | ((uint32_t)__bfloat16_as_ushort(a1) << 16);
            lo16[p] = (uint32_t)__bfloat16_as_ushort(c0) | ((uint32_t)__bfloat16_as_ushort(c1) << 16);
        }
        __syncthreads();   // hrow/sW2p reads done before sA overwrite

        uint32_t* row = (uint32_t*)smem + eL * SA_ST;
#pragma unroll
        for (int p = 0; p < 16; p++) row[16 * half + p] = hi16[p];
#pragma unroll
        for (int p = 0; p < 16; p++) row[32 + 16 * half + p] = lo16[p];
    }
    __syncthreads();

    // A fragments: 8 distinct k-frags (0-3 hi, 4-7 lo), conflict-free LDS
    uint32_t af[8][4];
    {
        const uint32_t* sA = (const uint32_t*)smem;
        const int r0 = (16 * w + g) * SA_ST;
        const int r1 = (16 * w + g + 8) * SA_ST;
#pragma unroll
        for (int kf = 0; kf < 8; kf++) {
            const int ko = kf * 8 + tig;
            af[kf][0] = sA[r0 + ko];
            af[kf][1] = sA[r1 + ko];
            af[kf][2] = sA[r0 + ko + 4];
            af[kf][3] = sA[r1 + ko + 4];
        }
    }
    __syncthreads();

    // stage basis + b3 + B chunk 0 (cp.async)
    for (int i = t; i < EPC * 27; i += 256) {
        const int e = i / 27, r = i - 27 * e;
        const int dd = r / 9, rr = r - 9 * dd;
        sbas[e * 40 + dd * 12 + rr] = basis[(size_t)(e0 + e) * 27 + r];
    }
    for (int i = t; i < R_DIM; i += 256) sb3[i] = b3[i];
#pragma unroll
    for (int q4 = 0; q4 < 3; q4++) {
        const int i = q4 * 256 + t;
        const int row = i >> 4, qq = i & 15;
        cp_async16(sB_u + row * (BST2 * 2) + qq * 16,
                   g_bbf + (size_t)row * KB + qq * 8);
    }
    CP_COMMIT();
    CP_WAIT0();
    __syncthreads();

    // TP index bases (period-9 structure: idx_{it+9} = idx_it + 64*36)
    const int e_base = t / 36;
    const int rem_base = t - 36 * e_base;

    // ================= main loop: 16 chunks ================================
#pragma unroll 1
    for (int c = 0; c < NCH; c++) {
        // ---- GEMM: 6 n-tiles, 2 at a time; bhi frags reused for 2 terms ----
#pragma unroll 1
        for (int j = 0; j < 6; j += 2) {
            const __nv_bfloat16* br0 = sB + (j * 8 + g) * BST2;
            const __nv_bfloat16* br1 = br0 + 8 * BST2;
            float d0 = 0.f, d1 = 0.f, d2 = 0.f, d3 = 0.f;
            float f0 = 0.f, f1 = 0.f, f2 = 0.f, f3 = 0.f;
#pragma unroll
            for (int kb = 0; kb < 4; kb++) {         // bhi: ahi*bhi + alo*bhi
                const int ke = kb * 16 + 2 * tig;
                const uint32_t b00 = *(const uint32_t*)(br0 + ke);
                const uint32_t b01 = *(const uint32_t*)(br0 + ke + 8);
                const uint32_t b10 = *(const uint32_t*)(br1 + ke);
                const uint32_t b11 = *(const uint32_t*)(br1 + ke + 8);
                mma_bf16(d0, d1, d2, d3, af[kb][0], af[kb][1], af[kb][2], af[kb][3], b00, b01);
                mma_bf16(f0, f1, f2, f3, af[kb][0], af[kb][1], af[kb][2], af[kb][3], b10, b11);
                mma_bf16(d0, d1, d2, d3, af[kb+4][0], af[kb+4][1], af[kb+4][2], af[kb+4][3], b00, b01);
                mma_bf16(f0, f1, f2, f3, af[kb+4][0], af[kb+4][1], af[kb+4][2], af[kb+4][3], b10, b11);
            }
#pragma unroll
            for (int kb = 0; kb < 4; kb++) {         // blo: ahi*blo
                const int ke = 64 + kb * 16 + 2 * tig;
                const uint32_t b00 = *(const uint32_t*)(br0 + ke);
                const uint32_t b01 = *(const uint32_t*)(br0 + ke + 8);
                const uint32_t b10 = *(const uint32_t*)(br1 + ke);
                const uint32_t b11 = *(const uint32_t*)(br1 + ke + 8);
                mma_bf16(d0, d1, d2, d3, af[kb][0], af[kb][1], af[kb][2], af[kb][3], b00, b01);
                mma_bf16(f0, f1, f2, f3, af[kb][0], af[kb][1], af[kb][2], af[kb][3], b10, b11);
            }
            const int eL = 16 * w + g;
#pragma unroll
            for (int tt = 0; tt < 2; tt++) {
                const int cc0 = (j + tt) * 8 + 2 * tig;
                const int cc1 = cc0 + 1;
                const float bs0 = sb3[c * CCOLS + cc0];
                const float bs1 = sb3[c * CCOLS + cc1];
                const int a0 = (cc0 / 3) * 4 + (cc0 % 3);
                const int a1 = (cc1 / 3) * 4 + (cc1 % 3);
                rbuf[eL * RBS + a0]       = (tt ? f0 : d0) + bs0;
                rbuf[eL * RBS + a1]       = (tt ? f1 : d1) + bs1;
                rbuf[(eL + 8) * RBS + a0] = (tt ? f2 : d2) + bs0;
                rbuf[(eL + 8) * RBS + a1] = (tt ? f3 : d3) + bs1;
            }
        }
        __syncthreads();   // GEMM done reading sB; rbuf ready

        // ---- prefetch next B chunk straight into sB (lands during TP) ----
        if (c + 1 < NCH) {
#pragma unroll
            for (int q4 = 0; q4 < 3; q4++) {
                const int i = q4 * 256 + t;
                const int row = i >> 4, qq = i & 15;
                cp_async16(sB_u + row * (BST2 * 2) + qq * 16,
                           g_bbf + (size_t)((c + 1) * CCOLS + row) * KB + qq * 8);
            }
            CP_COMMIT();
        }

        // ---- TP phase: 128 edges x 144 floats (o = c) ----
        {
            int e = e_base, rem = rem_base;
#pragma unroll
            for (int it = 0; it < 9; it++) {
                const int dd = (rem >= 24) ? 2 : ((rem >= 12) ? 1 : 0);
                const int pos = rem - 12 * dd;
                const int p3 = (pos * 11) >> 5;          // pos/3 for pos<12
                const int i0 = pos + p3;                 // (4*pos)/3
                const int m0 = pos - 3 * p3;
                const int s4 = 4 * pos;
#pragma unroll
                for (int hh = 0; hh < 2; hh++) {
                    const int ee = e + 64 * hh;
                    const float* rrow = rbuf + ee * RBS + i0 * 4;
                    const float4 ra  = *(const float4*)(rrow);
                    const float4 rbt = *(const float4*)(rrow + 4);
                    const float* B = sbas + ee * 40 + dd * 12;
                    const float4 b04 = *(const float4*)(B);
                    const float4 b14 = *(const float4*)(B + 4);
                    const float  b8  = B[8];
                    const float da0 = ra.x * b04.x + ra.y * b04.y + ra.z * b04.z;
                    const float da1 = ra.x * b04.w + ra.y * b14.x + ra.z * b14.y;
                    const float da2 = ra.x * b14.z + ra.y * b14.w + ra.z * b8;
                    const float db0 = rbt.x * b04.x + rbt.y * b04.y + rbt.z * b04.z;
                    const float db1 = rbt.x * b04.w + rbt.y * b14.x + rbt.z * b14.y;
                    const float db2 = rbt.x * b14.z + rbt.y * b14.w + rbt.z * b8;
                    float4 ov;
                    ov.x = (m0 == 0) ? da0 : ((m0 == 1) ? da1 : da2);
                    ov.y = (m0 == 0) ? da1 : ((m0 == 1) ? da2 : db0);
                    ov.z = (m0 == 0) ? da2 : ((m0 == 1) ? db0 : db1);
                    ov.w = (m0 == 0) ? db0 : ((m0 == 1) ? db1 : db2);
                    *(float4*)(out + (size_t)(e0 + ee) * OUT_PER_EDGE + c * 144 + dd * 48 + s4) = ov;
                }
                e += 7; rem += 4;
                if (rem >= 36) { rem -= 36; e += 1; }
            }
        }
        CP_WAIT0();
        __syncthreads();   // sB refill visible; rbuf free
    }
}

// ---------------------------------------------------------------------------
extern "C" void kernel_launch(void* const* d_in, const int* in_sizes, int n_in,
                              void* d_out, int out_size)
{
    const float* feat  = (const float*)d_in[0];
    const float* basis = (const float*)d_in[1];
    const float* W1    = (const float*)d_in[2];
    const float* b1    = (const float*)d_in[3];
    const float* g1    = (const float*)d_in[4];
    const float* W2    = (const float*)d_in[5];
    const float* b2    = (const float*)d_in[6];
    const float* g2    = (const float*)d_in[7];
    const float* W3    = (const float*)d_in[8];
    const float* b3    = (const float*)d_in[9];
    float* out = (float*)d_out;

    cudaFuncSetAttribute(k2_fused, cudaFuncAttributeMaxDynamicSharedMemorySize, SM_TOTAL);

    k0_prep<<<(R_DIM * KB + 255) / 256, 256>>>(W3);
    k2_fused<<<NCTA, 256, SM_TOTAL>>>(feat, basis, W1, b1, g1, W2, b2, g2, b3, out);
}